// round 5
// baseline (speedup 1.0000x reference)
#include <cuda_runtime.h>
#include <cuda_bf16.h>
#include <cstdint>

// Problem constants
#define B_  4
#define S_  8192
#define D_  1024
#define H_  16
#define DK_ 64
#define EPSF 1e-6f
#define MROWS (B_ * S_)

// ---------------------------------------------------------------------------
// Scratch (device globals — no runtime allocation allowed)
// ---------------------------------------------------------------------------
__device__ float g_Q[(size_t)B_ * S_ * D_];
__device__ float g_K[(size_t)B_ * S_ * D_];
__device__ float g_V[(size_t)B_ * S_ * D_];
__device__ float g_kv[(size_t)B_ * H_ * DK_ * DK_];
__device__ float g_ktot[B_ * H_];
__device__ __nv_bfloat16 g_Wh[4ull * 1024 * 1024];
__device__ __nv_bfloat16 g_Wl[4ull * 1024 * 1024];
__device__ __nv_bfloat16 g_Ah[(size_t)MROWS * 1024];
__device__ __nv_bfloat16 g_Al[(size_t)MROWS * 1024];

// ---------------------------------------------------------------------------
// PTX helpers (sm_80-level PTX only — ptxas target is sm_103 non-'a')
// ---------------------------------------------------------------------------
__device__ __forceinline__ uint32_t smem_u32(const void* p) {
    uint32_t a;
    asm("{ .reg .u64 t; cvta.to.shared.u64 t, %1; cvt.u32.u64 %0, t; }"
        : "=r"(a) : "l"(p));
    return a;
}
__device__ __forceinline__ void ldsm_x4(uint32_t& r0, uint32_t& r1,
                                        uint32_t& r2, uint32_t& r3, uint32_t addr) {
    asm volatile("ldmatrix.sync.aligned.m8n8.x4.shared.b16 {%0,%1,%2,%3}, [%4];"
                 : "=r"(r0), "=r"(r1), "=r"(r2), "=r"(r3) : "r"(addr));
}
__device__ __forceinline__ void mma_bf16(float* c, const uint32_t* a, const uint32_t* b) {
    asm volatile(
        "mma.sync.aligned.m16n8k16.row.col.f32.bf16.bf16.f32 "
        "{%0,%1,%2,%3}, {%4,%5,%6,%7}, {%8,%9}, {%0,%1,%2,%3};"
        : "+f"(c[0]), "+f"(c[1]), "+f"(c[2]), "+f"(c[3])
        : "r"(a[0]), "r"(a[1]), "r"(a[2]), "r"(a[3]), "r"(b[0]), "r"(b[1]));
}
__device__ __forceinline__ void cpa16(uint32_t dst, const void* src) {
    asm volatile("cp.async.ca.shared.global [%0], [%1], 16;" :: "r"(dst), "l"(src));
}
__device__ __forceinline__ void cpa_commit() {
    asm volatile("cp.async.commit_group;" ::: "memory");
}
__device__ __forceinline__ void cpa_wait2() {
    asm volatile("cp.async.wait_group 2;" ::: "memory");
}
__device__ __forceinline__ uint32_t pack_hi(float x, float y) {
    unsigned short hx = __bfloat16_as_ushort(__float2bfloat16(x));
    unsigned short hy = __bfloat16_as_ushort(__float2bfloat16(y));
    return ((uint32_t)hy << 16) | hx;
}
__device__ __forceinline__ uint32_t pack_lo(float x, float y) {
    float rx = x - __bfloat162float(__float2bfloat16(x));
    float ry = y - __bfloat162float(__float2bfloat16(y));
    unsigned short lx = __bfloat16_as_ushort(__float2bfloat16(rx));
    unsigned short ly = __bfloat16_as_ushort(__float2bfloat16(ry));
    return ((uint32_t)ly << 16) | lx;
}

// ---------------------------------------------------------------------------
// fp32 -> bf16 hi/lo split (used for weights AND activations)
// ---------------------------------------------------------------------------
__global__ __launch_bounds__(256) void split_w(
    const float* __restrict__ W, __nv_bfloat16* __restrict__ Wh,
    __nv_bfloat16* __restrict__ Wl)
{
    int i = (blockIdx.x * 256 + threadIdx.x) * 4;
    float4 v = *reinterpret_cast<const float4*>(W + i);
    uint32_t* whp = reinterpret_cast<uint32_t*>(Wh + i);
    uint32_t* wlp = reinterpret_cast<uint32_t*>(Wl + i);
    whp[0] = pack_hi(v.x, v.y);
    whp[1] = pack_hi(v.z, v.w);
    wlp[0] = pack_lo(v.x, v.y);
    wlp[1] = pack_lo(v.z, v.w);
}

// ---------------------------------------------------------------------------
// HMMA GEMM: C[M,1024] = A[M,1024] @ W[1024,1024]^T  (A,W pre-split bf16 hi/lo)
// CTA tile 128x128, BK=32, 8 warps of 64x32, 3-pass split, 3-stage cp.async.
// Smem: 64B rows with XOR-chunk swizzle -> conflict-free ldmatrix, no padding.
// ---------------------------------------------------------------------------
#define SUBT   8192                    // 128 rows * 64B
#define OFF_AH 0
#define OFF_AL (1 * SUBT)
#define OFF_WH (2 * SUBT)
#define OFF_WL (3 * SUBT)
#define STAGE  (4 * SUBT)              // 32768
#define NSTG   3
#define SMEMSZ (NSTG * STAGE)          // 98304

__global__ __launch_bounds__(256, 2) void gemm_tc(
    const __nv_bfloat16* __restrict__ Ah,
    const __nv_bfloat16* __restrict__ Al,
    const __nv_bfloat16* __restrict__ Wh,
    const __nv_bfloat16* __restrict__ Wl,
    float* __restrict__ C, int act)
{
    extern __shared__ __align__(128) char smc[];
    const uint32_t sb0 = smem_u32(smc);
    const int tid = threadIdx.x;
    const int lane = tid & 31, w = tid >> 5;
    const int wm = w >> 2, wn = w & 3;
    const int bx = blockIdx.x, by = blockIdx.y;

    const __nv_bfloat16* AhB = Ah + (size_t)by * 128 * 1024;
    const __nv_bfloat16* AlB = Al + (size_t)by * 128 * 1024;
    const __nv_bfloat16* WhB = Wh + (size_t)bx * 128 * 1024;
    const __nv_bfloat16* WlB = Wl + (size_t)bx * 128 * 1024;

    float acc[4][4][4];
#pragma unroll
    for (int i = 0; i < 4; i++)
#pragma unroll
        for (int j = 0; j < 4; j++)
#pragma unroll
            for (int q = 0; q < 4; q++) acc[i][j][q] = 0.f;

    uint32_t fa[4][4], fbH[4][2], fbL[4][2];

    // cp.async thread mapping: idx -> row = idx>>2, chunk = idx&3 (16B chunks)
    const int cprow0 = (tid * 2) >> 3;          // rows for idx=tid*2? no — see loop
    (void)cprow0;

    // ldmatrix per-lane addressing (swizzle: phys_chunk = chunk ^ ((row>>1)&3))
    const int aRowBase = wm * 64 + (lane & 15);
    const int aHalf    = lane >> 4;                       // 0/1 -> k 16B half
    const int swA      = (aRowBase >> 1) & 3;
    const uint32_t aByte = (uint32_t)aRowBase * 64;

    const int bRowBase = wn * 32 + ((lane >> 4) << 3) + (lane & 7);
    const int bHalf    = (lane >> 3) & 1;
    const int swB      = (bRowBase >> 1) & 3;
    const uint32_t bByte = (uint32_t)bRowBase * 64;

    auto IssueChunk = [&](int c) {
        if (c < 32) {
            const uint32_t sb = sb0 + (uint32_t)(c % NSTG) * STAGE;
            const int k0 = c * 32;
#pragma unroll
            for (int i = 0; i < 2; i++) {
                int idx = tid + i * 256;            // 0..511
                int r = idx >> 2, ch = idx & 3;
                uint32_t dst = (uint32_t)(r * 64 + ((ch ^ ((r >> 1) & 3)) << 4));
                size_t src = (size_t)r * 1024 + k0 + ch * 8;
                cpa16(sb + OFF_AH + dst, AhB + src);
                cpa16(sb + OFF_AL + dst, AlB + src);
                cpa16(sb + OFF_WH + dst, WhB + src);
                cpa16(sb + OFF_WL + dst, WlB + src);
            }
        }
        cpa_commit();
    };
    auto LdA = [&](uint32_t base) {
#pragma unroll
        for (int mt = 0; mt < 4; mt++)
            ldsm_x4(fa[mt][0], fa[mt][1], fa[mt][2], fa[mt][3],
                    base + (uint32_t)mt * 1024);
    };
    auto LdB = [&](uint32_t b[4][2], uint32_t base) {
        ldsm_x4(b[0][0], b[0][1], b[1][0], b[1][1], base);
        ldsm_x4(b[2][0], b[2][1], b[3][0], b[3][1], base + 1024);
    };
    auto MmaAll = [&](uint32_t b[4][2]) {
#pragma unroll
        for (int mt = 0; mt < 4; mt++)
#pragma unroll
            for (int nf = 0; nf < 4; nf++)
                mma_bf16(acc[mt][nf], fa[mt], b[nf]);
    };

    // Prologue: fill 3 stages
    IssueChunk(0);
    IssueChunk(1);
    IssueChunk(2);

    for (int c = 0; c < 32; c++) {
        const uint32_t sb = sb0 + (uint32_t)(c % NSTG) * STAGE;
        cpa_wait2();
        __syncthreads();

#pragma unroll
        for (int ks = 0; ks < 2; ks++) {
            const uint32_t ca = (uint32_t)(((2 * ks + aHalf) ^ swA) << 4);
            const uint32_t cb = (uint32_t)(((2 * ks + bHalf) ^ swB) << 4);
            LdA(sb + OFF_AH + aByte + ca);
            LdB(fbH, sb + OFF_WH + bByte + cb);
            LdB(fbL, sb + OFF_WL + bByte + cb);
            MmaAll(fbH);                 // Ah * Wh
            MmaAll(fbL);                 // Ah * Wl
            LdA(sb + OFF_AL + aByte + ca);
            MmaAll(fbH);                 // Al * Wh
        }
        __syncthreads();
        IssueChunk(c + 3);
    }

    // Epilogue
    const int mBase = by * 128 + wm * 64 + (lane >> 2);
    const int nBase = bx * 128 + wn * 32 + (lane & 3) * 2;
#pragma unroll
    for (int mt = 0; mt < 4; mt++) {
#pragma unroll
        for (int nf = 0; nf < 4; nf++) {
            int m = mBase + mt * 16;
            int n = nBase + nf * 8;
            float2 v0 = make_float2(acc[mt][nf][0], acc[mt][nf][1]);
            float2 v1 = make_float2(acc[mt][nf][2], acc[mt][nf][3]);
            if (act) {
                v0.x = fmaxf(v0.x, 0.f) + EPSF; v0.y = fmaxf(v0.y, 0.f) + EPSF;
                v1.x = fmaxf(v1.x, 0.f) + EPSF; v1.y = fmaxf(v1.y, 0.f) + EPSF;
            }
            *reinterpret_cast<float2*>(C + (size_t)m * 1024 + n) = v0;
            *reinterpret_cast<float2*>(C + (size_t)(m + 8) * 1024 + n) = v1;
        }
    }
}

// ---------------------------------------------------------------------------
// Zero kv / ktot
// ---------------------------------------------------------------------------
__global__ void zero_kv()
{
    int i = blockIdx.x * blockDim.x + threadIdx.x;
    if (i < B_ * H_ * DK_ * DK_) g_kv[i] = 0.f;
    if (i < B_ * H_) g_ktot[i] = 0.f;
}

// ---------------------------------------------------------------------------
// kv[b,h,d,e] = sum_s K[b,s,h,d] * V[b,s,h,e] ; ktot[b,h] = sum K
// ---------------------------------------------------------------------------
#define SCHUNK 512
#define SSTAGE 8

__global__ __launch_bounds__(256) void kv_reduce(
    const float* __restrict__ Kb, const float* __restrict__ Vb)
{
    const int bh = blockIdx.x;
    const int b = bh >> 4, h = bh & 15;
    const int s0 = blockIdx.y * SCHUNK;

    __shared__ float sK[SSTAGE][DK_];
    __shared__ float sV[SSTAGE][DK_];
    __shared__ float red[256];

    const int tid = threadIdx.x;
    const int d0 = (tid >> 4) << 2;
    const int e0 = (tid & 15) << 2;

    float acc[4][4];
#pragma unroll
    for (int i = 0; i < 4; i++)
#pragma unroll
        for (int j = 0; j < 4; j++) acc[i][j] = 0.f;

    float ksum = 0.f;
    const size_t base = ((size_t)b * S_ + s0) * D_ + h * DK_;

    for (int so = 0; so < SCHUNK; so += SSTAGE) {
#pragma unroll
        for (int i = 0; i < 2; i++) {
            int idx = tid + i * 256;
            int sr = idx >> 6, dd = idx & 63;
            size_t off = base + (size_t)(so + sr) * D_ + dd;
            float kval = Kb[off];
            sK[sr][dd] = kval; ksum += kval;
            sV[sr][dd] = Vb[off];
        }
        __syncthreads();
#pragma unroll
        for (int sr = 0; sr < SSTAGE; sr++) {
            float kd[4], ve[4];
#pragma unroll
            for (int i = 0; i < 4; i++) { kd[i] = sK[sr][d0 + i]; ve[i] = sV[sr][e0 + i]; }
#pragma unroll
            for (int i = 0; i < 4; i++)
#pragma unroll
                for (int j = 0; j < 4; j++)
                    acc[i][j] = fmaf(kd[i], ve[j], acc[i][j]);
        }
        __syncthreads();
    }

    float* kvp = g_kv + (size_t)bh * DK_ * DK_;
#pragma unroll
    for (int i = 0; i < 4; i++)
#pragma unroll
        for (int j = 0; j < 4; j++)
            atomicAdd(&kvp[(d0 + i) * DK_ + e0 + j], acc[i][j]);

    red[tid] = ksum;
    __syncthreads();
    for (int off = 128; off > 0; off >>= 1) {
        if (tid < off) red[tid] += red[tid + off];
        __syncthreads();
    }
    if (tid == 0) atomicAdd(&g_ktot[bh], red[0]);
}

// ---------------------------------------------------------------------------
// P = (Q @ kv) / (rowsum(Q) * ktot + eps)  -> emitted pre-split as bf16 hi/lo
// ---------------------------------------------------------------------------
#define SC3 256

__global__ __launch_bounds__(256) void apply_kv(
    const float* __restrict__ Qb,
    __nv_bfloat16* __restrict__ Ph, __nv_bfloat16* __restrict__ Pl)
{
    const int bh = blockIdx.x;
    const int b = bh >> 4, h = bh & 15;

    __shared__ float skv[DK_ * DK_];
    __shared__ float sQ[4][DK_];

    for (int i = threadIdx.x; i < DK_ * DK_; i += 256)
        skv[i] = g_kv[(size_t)bh * DK_ * DK_ + i];
    __syncthreads();

    const float ktv = g_ktot[bh];
    const int grp = threadIdx.x >> 6;
    const int e   = threadIdx.x & 63;
    const int s0  = blockIdx.y * SC3;

    for (int si = 0; si < SC3; si += 4) {
        int s = s0 + si + grp;
        size_t off = ((size_t)b * S_ + s) * D_ + h * DK_;
        sQ[grp][e] = Qb[off + e];
        __syncthreads();
        float rsum = 0.f, acc = 0.f;
#pragma unroll
        for (int d = 0; d < DK_; d++) {
            float qd = sQ[grp][d];
            rsum += qd;
            acc = fmaf(qd, skv[d * DK_ + e], acc);
        }
        float val = acc * (1.f / (rsum * ktv + EPSF));
        __nv_bfloat16 hv = __float2bfloat16(val);
        Ph[off + e] = hv;
        Pl[off + e] = __float2bfloat16(val - __bfloat162float(hv));
        __syncthreads();
    }
}

// ---------------------------------------------------------------------------
// Launch
// ---------------------------------------------------------------------------
extern "C" void kernel_launch(void* const* d_in, const int* in_sizes, int n_in,
                              void* d_out, int out_size)
{
    const float* q  = (const float*)d_in[0];
    const float* k  = (const float*)d_in[1];
    const float* v  = (const float*)d_in[2];
    const float* Wq = (const float*)d_in[3];
    const float* Wk = (const float*)d_in[4];
    const float* Wv = (const float*)d_in[5];
    const float* Wo = (const float*)d_in[6];
    float* out = (float*)d_out;

    float *Qb, *Kb, *Vb;
    __nv_bfloat16 *whp, *wlp, *ahp, *alp;
    cudaGetSymbolAddress((void**)&Qb, g_Q);
    cudaGetSymbolAddress((void**)&Kb, g_K);
    cudaGetSymbolAddress((void**)&Vb, g_V);
    cudaGetSymbolAddress((void**)&whp, g_Wh);
    cudaGetSymbolAddress((void**)&wlp, g_Wl);
    cudaGetSymbolAddress((void**)&ahp, g_Ah);
    cudaGetSymbolAddress((void**)&alp, g_Al);

    cudaFuncSetAttribute(gemm_tc, cudaFuncAttributeMaxDynamicSharedMemorySize,
                         SMEMSZ);

    const size_t WSTRIDE = 1024ull * 1024ull;
    const int ABLK = (int)((size_t)MROWS * 1024 / (256 * 4));   // 32768

    // Pre-split weights to bf16 hi/lo
    split_w<<<1024, 256>>>(Wq, whp + 0 * WSTRIDE, wlp + 0 * WSTRIDE);
    split_w<<<1024, 256>>>(Wk, whp + 1 * WSTRIDE, wlp + 1 * WSTRIDE);
    split_w<<<1024, 256>>>(Wv, whp + 2 * WSTRIDE, wlp + 2 * WSTRIDE);
    split_w<<<1024, 256>>>(Wo, whp + 3 * WSTRIDE, wlp + 3 * WSTRIDE);

    dim3 gg(8, MROWS / 128);   // x = N tiles (fast), y = M tiles

    split_w<<<ABLK, 256>>>(q, ahp, alp);
    gemm_tc<<<gg, 256, SMEMSZ>>>(ahp, alp, whp + 0 * WSTRIDE, wlp + 0 * WSTRIDE, Qb, 1);
    split_w<<<ABLK, 256>>>(k, ahp, alp);
    gemm_tc<<<gg, 256, SMEMSZ>>>(ahp, alp, whp + 1 * WSTRIDE, wlp + 1 * WSTRIDE, Kb, 1);
    split_w<<<ABLK, 256>>>(v, ahp, alp);
    gemm_tc<<<gg, 256, SMEMSZ>>>(ahp, alp, whp + 2 * WSTRIDE, wlp + 2 * WSTRIDE, Vb, 0);

    zero_kv<<<(B_ * H_ * DK_ * DK_ + 255) / 256, 256>>>();
    kv_reduce<<<dim3(B_ * H_, S_ / SCHUNK), 256>>>(Kb, Vb);
    apply_kv<<<dim3(B_ * H_, S_ / SC3), 256>>>(Qb, ahp, alp);

    gemm_tc<<<gg, 256, SMEMSZ>>>(ahp, alp, whp + 3 * WSTRIDE, wlp + 3 * WSTRIDE, out, 0);
}

// round 6
// speedup vs baseline: 1.1139x; 1.1139x over previous
#include <cuda_runtime.h>
#include <cuda_bf16.h>
#include <cstdint>

// Problem constants
#define B_  4
#define S_  8192
#define D_  1024
#define H_  16
#define DK_ 64
#define EPSF 1e-6f
#define MROWS (B_ * S_)

// ---------------------------------------------------------------------------
// Scratch (device globals — no runtime allocation allowed)
// ---------------------------------------------------------------------------
__device__ float g_Q[(size_t)B_ * S_ * D_];
__device__ float g_K[(size_t)B_ * S_ * D_];
__device__ float g_V[(size_t)B_ * S_ * D_];
__device__ float g_kv[(size_t)B_ * H_ * DK_ * DK_];
__device__ float g_ktot[B_ * H_];
__device__ __nv_bfloat16 g_Wh[4ull * 1024 * 1024];
__device__ __nv_bfloat16 g_Wl[4ull * 1024 * 1024];
__device__ __nv_bfloat16 g_Ph[(size_t)MROWS * 1024];
__device__ __nv_bfloat16 g_Pl[(size_t)MROWS * 1024];

// ---------------------------------------------------------------------------
// PTX helpers (sm_80-level PTX only — ptxas target is sm_103 non-'a')
// ---------------------------------------------------------------------------
__device__ __forceinline__ uint32_t smem_u32(const void* p) {
    uint32_t a;
    asm("{ .reg .u64 t; cvta.to.shared.u64 t, %1; cvt.u32.u64 %0, t; }"
        : "=r"(a) : "l"(p));
    return a;
}
__device__ __forceinline__ void ldsm_x4(uint32_t& r0, uint32_t& r1,
                                        uint32_t& r2, uint32_t& r3, uint32_t addr) {
    asm volatile("ldmatrix.sync.aligned.m8n8.x4.shared.b16 {%0,%1,%2,%3}, [%4];"
                 : "=r"(r0), "=r"(r1), "=r"(r2), "=r"(r3) : "r"(addr));
}
__device__ __forceinline__ void mma_bf16(float* c, const uint32_t* a, const uint32_t* b) {
    asm volatile(
        "mma.sync.aligned.m16n8k16.row.col.f32.bf16.bf16.f32 "
        "{%0,%1,%2,%3}, {%4,%5,%6,%7}, {%8,%9}, {%0,%1,%2,%3};"
        : "+f"(c[0]), "+f"(c[1]), "+f"(c[2]), "+f"(c[3])
        : "r"(a[0]), "r"(a[1]), "r"(a[2]), "r"(a[3]), "r"(b[0]), "r"(b[1]));
}
__device__ __forceinline__ void cpa16(uint32_t dst, const void* src) {
    asm volatile("cp.async.ca.shared.global [%0], [%1], 16;" :: "r"(dst), "l"(src));
}
__device__ __forceinline__ void cpa_commit() {
    asm volatile("cp.async.commit_group;" ::: "memory");
}
__device__ __forceinline__ void cpa_wait1() {
    asm volatile("cp.async.wait_group 1;" ::: "memory");
}
__device__ __forceinline__ void cpa_wait0() {
    asm volatile("cp.async.wait_group 0;" ::: "memory");
}
__device__ __forceinline__ void sts64(uint32_t addr, uint32_t a, uint32_t b) {
    asm volatile("st.shared.v2.b32 [%0], {%1, %2};"
                 :: "r"(addr), "r"(a), "r"(b) : "memory");
}
__device__ __forceinline__ uint32_t pack_hi(float x, float y) {
    unsigned short hx = __bfloat16_as_ushort(__float2bfloat16(x));
    unsigned short hy = __bfloat16_as_ushort(__float2bfloat16(y));
    return ((uint32_t)hy << 16) | hx;
}
__device__ __forceinline__ uint32_t pack_lo(float x, float y) {
    float rx = x - __bfloat162float(__float2bfloat16(x));
    float ry = y - __bfloat162float(__float2bfloat16(y));
    unsigned short lx = __bfloat16_as_ushort(__float2bfloat16(rx));
    unsigned short ly = __bfloat16_as_ushort(__float2bfloat16(ry));
    return ((uint32_t)ly << 16) | lx;
}

// ---------------------------------------------------------------------------
// Weight pre-split: two fp32 matrices -> bf16 hi/lo each (one launch for two)
// ---------------------------------------------------------------------------
__global__ __launch_bounds__(256) void split_w2(
    const float* __restrict__ W0, __nv_bfloat16* __restrict__ Wh0,
    __nv_bfloat16* __restrict__ Wl0,
    const float* __restrict__ W1, __nv_bfloat16* __restrict__ Wh1,
    __nv_bfloat16* __restrict__ Wl1)
{
    int half = blockIdx.x >> 10;           // 0 or 1 (1024 blocks each)
    int i = ((blockIdx.x & 1023) * 256 + threadIdx.x) * 4;
    const float* W = half ? W1 : W0;
    __nv_bfloat16* Wh = half ? Wh1 : Wh0;
    __nv_bfloat16* Wl = half ? Wl1 : Wl0;
    float4 v = *reinterpret_cast<const float4*>(W + i);
    uint32_t* whp = reinterpret_cast<uint32_t*>(Wh + i);
    uint32_t* wlp = reinterpret_cast<uint32_t*>(Wl + i);
    whp[0] = pack_hi(v.x, v.y);
    whp[1] = pack_hi(v.z, v.w);
    wlp[0] = pack_lo(v.x, v.y);
    wlp[1] = pack_lo(v.z, v.w);
}

// ---------------------------------------------------------------------------
// HMMA GEMM: C[M,1024] = A[M,1024] @ W[1024,1024]^T
// CTA tile 128x128, BK=32, 8 warps of 64x32, bf16 3-pass split, 2-stage.
// Smem: 64B rows, XOR-chunk swizzle (conflict-free ldmatrix, no padding).
// APRE=0: A fp32, split in kernel (LDG+STS). APRE=1: A pre-split bf16 hi/lo.
// ---------------------------------------------------------------------------
#define SUBT   8192                    // 128 rows * 64B
#define OFF_AH 0
#define OFF_AL (1 * SUBT)
#define OFF_WH (2 * SUBT)
#define OFF_WL (3 * SUBT)
#define STAGE  (4 * SUBT)              // 32768
#define SMEMSZ (2 * STAGE)             // 65536

template <int APRE>
__global__ __launch_bounds__(256, 2) void gemm_tc(
    const float* __restrict__ A32,
    const __nv_bfloat16* __restrict__ Ahp,
    const __nv_bfloat16* __restrict__ Alp,
    const __nv_bfloat16* __restrict__ Wh,
    const __nv_bfloat16* __restrict__ Wl,
    float* __restrict__ C, int act)
{
    extern __shared__ __align__(128) char smc[];
    const uint32_t sb0 = smem_u32(smc);
    const int tid = threadIdx.x;
    const int lane = tid & 31, w = tid >> 5;
    const int wm = w >> 2, wn = w & 3;
    const int bx = blockIdx.x, by = blockIdx.y;

    const float* Ab = A32 + (size_t)by * 128 * 1024;
    const __nv_bfloat16* AhB = Ahp + (size_t)by * 128 * 1024;
    const __nv_bfloat16* AlB = Alp + (size_t)by * 128 * 1024;
    const __nv_bfloat16* WhB = Wh + (size_t)bx * 128 * 1024;
    const __nv_bfloat16* WlB = Wl + (size_t)bx * 128 * 1024;

    float acc[4][4][4];
#pragma unroll
    for (int i = 0; i < 4; i++)
#pragma unroll
        for (int j = 0; j < 4; j++)
#pragma unroll
            for (int q = 0; q < 4; q++) acc[i][j][q] = 0.f;

    uint32_t fa[4][4], fbH[4][2], fbL[4][2];
    float4 areg[4];

    // ldmatrix addressing (swizzle: phys_chunk = chunk ^ ((row>>1)&3))
    const int aRowBase = wm * 64 + (lane & 15);
    const int aHalf    = lane >> 4;
    const int swA      = (aRowBase >> 1) & 3;
    const uint32_t aByte = (uint32_t)aRowBase * 64;

    const int bRowBase = wn * 32 + ((lane >> 4) << 3) + (lane & 7);
    const int bHalf    = (lane >> 3) & 1;
    const int swB      = (bRowBase >> 1) & 3;
    const uint32_t bByte = (uint32_t)bRowBase * 64;

    // --- A fp32 path helpers (APRE=0) ---
    auto LdgA = [&](int k0) {
#pragma unroll
        for (int i = 0; i < 4; i++) {
            int idx = tid + i * 256;           // 0..1023
            int r = idx >> 3, c4 = idx & 7;    // row, float4-pos
            areg[i] = *reinterpret_cast<const float4*>(
                Ab + (size_t)r * 1024 + k0 + c4 * 4);
        }
    };
    auto StsA = [&](uint32_t sb) {
#pragma unroll
        for (int i = 0; i < 4; i++) {
            int idx = tid + i * 256;
            int r = idx >> 3, c4 = idx & 7;
            int ch = c4 >> 1, sub = c4 & 1;
            uint32_t off = (uint32_t)(r * 64 + ((ch ^ ((r >> 1) & 3)) << 4) + sub * 8);
            float4 v = areg[i];
            sts64(sb + OFF_AH + off, pack_hi(v.x, v.y), pack_hi(v.z, v.w));
            sts64(sb + OFF_AL + off, pack_lo(v.x, v.y), pack_lo(v.z, v.w));
        }
    };
    auto CpW = [&](uint32_t sb, int k0) {
#pragma unroll
        for (int i = 0; i < 2; i++) {
            int idx = tid + i * 256;           // 0..511
            int r = idx >> 2, ch = idx & 3;
            uint32_t dst = (uint32_t)(r * 64 + ((ch ^ ((r >> 1) & 3)) << 4));
            size_t src = (size_t)r * 1024 + k0 + ch * 8;
            cpa16(sb + OFF_WH + dst, WhB + src);
            cpa16(sb + OFF_WL + dst, WlB + src);
        }
    };
    // --- A pre-split path (APRE=1): all four streams via cp.async ---
    auto CpAll = [&](uint32_t sb, int k0) {
#pragma unroll
        for (int i = 0; i < 2; i++) {
            int idx = tid + i * 256;
            int r = idx >> 2, ch = idx & 3;
            uint32_t dst = (uint32_t)(r * 64 + ((ch ^ ((r >> 1) & 3)) << 4));
            size_t src = (size_t)r * 1024 + k0 + ch * 8;
            cpa16(sb + OFF_AH + dst, AhB + src);
            cpa16(sb + OFF_AL + dst, AlB + src);
            cpa16(sb + OFF_WH + dst, WhB + src);
            cpa16(sb + OFF_WL + dst, WlB + src);
        }
    };

    auto LdA = [&](uint32_t base) {
#pragma unroll
        for (int mt = 0; mt < 4; mt++)
            ldsm_x4(fa[mt][0], fa[mt][1], fa[mt][2], fa[mt][3],
                    base + (uint32_t)mt * 1024);
    };
    auto LdB = [&](uint32_t b[4][2], uint32_t base) {
        ldsm_x4(b[0][0], b[0][1], b[1][0], b[1][1], base);
        ldsm_x4(b[2][0], b[2][1], b[3][0], b[3][1], base + 1024);
    };
    auto MmaAll = [&](uint32_t b[4][2]) {
#pragma unroll
        for (int mt = 0; mt < 4; mt++)
#pragma unroll
            for (int nf = 0; nf < 4; nf++)
                mma_bf16(acc[mt][nf], fa[mt], b[nf]);
    };

    // Prologue
    if (APRE) {
        CpAll(sb0, 0);           cpa_commit();
        CpAll(sb0 + STAGE, 32);  cpa_commit();
    } else {
        LdgA(0);
        StsA(sb0);
        CpW(sb0, 0);             cpa_commit();
        LdgA(32);
        CpW(sb0 + STAGE, 32);    cpa_commit();
    }

    for (int c = 0; c < 32; c++) {
        const uint32_t sb = sb0 + (uint32_t)(c & 1) * STAGE;
        if (c < 31) cpa_wait1(); else cpa_wait0();
        __syncthreads();

#pragma unroll
        for (int ks = 0; ks < 2; ks++) {
            const uint32_t ca = (uint32_t)(((2 * ks + aHalf) ^ swA) << 4);
            const uint32_t cb = (uint32_t)(((2 * ks + bHalf) ^ swB) << 4);
            LdA(sb + OFF_AH + aByte + ca);
            LdB(fbH, sb + OFF_WH + bByte + cb);
            LdB(fbL, sb + OFF_WL + bByte + cb);
            MmaAll(fbH);                 // Ah * Wh
            MmaAll(fbL);                 // Ah * Wl
            LdA(sb + OFF_AL + aByte + ca);
            MmaAll(fbH);                 // Al * Wh
        }
        __syncthreads();

        if (APRE) {
            if (c < 30) CpAll(sb, (c + 2) * 32);
            cpa_commit();
        } else {
            if (c < 31) StsA(sb0 + (uint32_t)((c + 1) & 1) * STAGE);
            if (c < 30) {
                LdgA((c + 2) * 32);
                CpW(sb, (c + 2) * 32);
            }
            cpa_commit();
        }
    }

    // Epilogue
    const int mBase = by * 128 + wm * 64 + (lane >> 2);
    const int nBase = bx * 128 + wn * 32 + (lane & 3) * 2;
#pragma unroll
    for (int mt = 0; mt < 4; mt++) {
#pragma unroll
        for (int nf = 0; nf < 4; nf++) {
            int m = mBase + mt * 16;
            int n = nBase + nf * 8;
            float2 v0 = make_float2(acc[mt][nf][0], acc[mt][nf][1]);
            float2 v1 = make_float2(acc[mt][nf][2], acc[mt][nf][3]);
            if (act) {
                v0.x = fmaxf(v0.x, 0.f) + EPSF; v0.y = fmaxf(v0.y, 0.f) + EPSF;
                v1.x = fmaxf(v1.x, 0.f) + EPSF; v1.y = fmaxf(v1.y, 0.f) + EPSF;
            }
            *reinterpret_cast<float2*>(C + (size_t)m * 1024 + n) = v0;
            *reinterpret_cast<float2*>(C + (size_t)(m + 8) * 1024 + n) = v1;
        }
    }
}

// ---------------------------------------------------------------------------
// Zero kv / ktot
// ---------------------------------------------------------------------------
__global__ void zero_kv()
{
    int i = blockIdx.x * blockDim.x + threadIdx.x;
    if (i < B_ * H_ * DK_ * DK_) g_kv[i] = 0.f;
    if (i < B_ * H_) g_ktot[i] = 0.f;
}

// ---------------------------------------------------------------------------
// kv[b,h,d,e] = sum_s K[b,s,h,d] * V[b,s,h,e] ; ktot[b,h] = sum K
// ---------------------------------------------------------------------------
#define SCHUNK 512
#define SSTAGE 8

__global__ __launch_bounds__(256) void kv_reduce(
    const float* __restrict__ Kb, const float* __restrict__ Vb)
{
    const int bh = blockIdx.x;
    const int b = bh >> 4, h = bh & 15;
    const int s0 = blockIdx.y * SCHUNK;

    __shared__ float sK[SSTAGE][DK_];
    __shared__ float sV[SSTAGE][DK_];
    __shared__ float red[256];

    const int tid = threadIdx.x;
    const int d0 = (tid >> 4) << 2;
    const int e0 = (tid & 15) << 2;

    float acc[4][4];
#pragma unroll
    for (int i = 0; i < 4; i++)
#pragma unroll
        for (int j = 0; j < 4; j++) acc[i][j] = 0.f;

    float ksum = 0.f;
    const size_t base = ((size_t)b * S_ + s0) * D_ + h * DK_;

    for (int so = 0; so < SCHUNK; so += SSTAGE) {
#pragma unroll
        for (int i = 0; i < 2; i++) {
            int idx = tid + i * 256;
            int sr = idx >> 6, dd = idx & 63;
            size_t off = base + (size_t)(so + sr) * D_ + dd;
            float kval = Kb[off];
            sK[sr][dd] = kval; ksum += kval;
            sV[sr][dd] = Vb[off];
        }
        __syncthreads();
#pragma unroll
        for (int sr = 0; sr < SSTAGE; sr++) {
            float kd[4], ve[4];
#pragma unroll
            for (int i = 0; i < 4; i++) { kd[i] = sK[sr][d0 + i]; ve[i] = sV[sr][e0 + i]; }
#pragma unroll
            for (int i = 0; i < 4; i++)
#pragma unroll
                for (int j = 0; j < 4; j++)
                    acc[i][j] = fmaf(kd[i], ve[j], acc[i][j]);
        }
        __syncthreads();
    }

    float* kvp = g_kv + (size_t)bh * DK_ * DK_;
#pragma unroll
    for (int i = 0; i < 4; i++)
#pragma unroll
        for (int j = 0; j < 4; j++)
            atomicAdd(&kvp[(d0 + i) * DK_ + e0 + j], acc[i][j]);

    red[tid] = ksum;
    __syncthreads();
    for (int off = 128; off > 0; off >>= 1) {
        if (tid < off) red[tid] += red[tid + off];
        __syncthreads();
    }
    if (tid == 0) atomicAdd(&g_ktot[bh], red[0]);
}

// ---------------------------------------------------------------------------
// P = (Q @ kv) / (rowsum(Q) * ktot + eps) -> emitted pre-split bf16 hi/lo
// ---------------------------------------------------------------------------
#define SC3 256

__global__ __launch_bounds__(256) void apply_kv(
    const float* __restrict__ Qb,
    __nv_bfloat16* __restrict__ Ph, __nv_bfloat16* __restrict__ Pl)
{
    const int bh = blockIdx.x;
    const int b = bh >> 4, h = bh & 15;

    __shared__ float skv[DK_ * DK_];
    __shared__ float sQ[4][DK_];

    for (int i = threadIdx.x; i < DK_ * DK_; i += 256)
        skv[i] = g_kv[(size_t)bh * DK_ * DK_ + i];
    __syncthreads();

    const float ktv = g_ktot[bh];
    const int grp = threadIdx.x >> 6;
    const int e   = threadIdx.x & 63;
    const int s0  = blockIdx.y * SC3;

    for (int si = 0; si < SC3; si += 4) {
        int s = s0 + si + grp;
        size_t off = ((size_t)b * S_ + s) * D_ + h * DK_;
        sQ[grp][e] = Qb[off + e];
        __syncthreads();
        float rsum = 0.f, acc = 0.f;
#pragma unroll
        for (int d = 0; d < DK_; d++) {
            float qd = sQ[grp][d];
            rsum += qd;
            acc = fmaf(qd, skv[d * DK_ + e], acc);
        }
        float val = acc * (1.f / (rsum * ktv + EPSF));
        __nv_bfloat16 hv = __float2bfloat16(val);
        Ph[off + e] = hv;
        Pl[off + e] = __float2bfloat16(val - __bfloat162float(hv));
        __syncthreads();
    }
}

// ---------------------------------------------------------------------------
// Launch
// ---------------------------------------------------------------------------
extern "C" void kernel_launch(void* const* d_in, const int* in_sizes, int n_in,
                              void* d_out, int out_size)
{
    const float* q  = (const float*)d_in[0];
    const float* k  = (const float*)d_in[1];
    const float* v  = (const float*)d_in[2];
    const float* Wq = (const float*)d_in[3];
    const float* Wk = (const float*)d_in[4];
    const float* Wv = (const float*)d_in[5];
    const float* Wo = (const float*)d_in[6];
    float* out = (float*)d_out;

    float *Qb, *Kb, *Vb;
    __nv_bfloat16 *whp, *wlp, *php, *plp;
    cudaGetSymbolAddress((void**)&Qb, g_Q);
    cudaGetSymbolAddress((void**)&Kb, g_K);
    cudaGetSymbolAddress((void**)&Vb, g_V);
    cudaGetSymbolAddress((void**)&whp, g_Wh);
    cudaGetSymbolAddress((void**)&wlp, g_Wl);
    cudaGetSymbolAddress((void**)&php, g_Ph);
    cudaGetSymbolAddress((void**)&plp, g_Pl);

    cudaFuncSetAttribute(gemm_tc<0>, cudaFuncAttributeMaxDynamicSharedMemorySize,
                         SMEMSZ);
    cudaFuncSetAttribute(gemm_tc<1>, cudaFuncAttributeMaxDynamicSharedMemorySize,
                         SMEMSZ);

    const size_t WS = 1024ull * 1024ull;
    dim3 gg(8, MROWS / 128);   // x = N tiles (fast), y = M tiles

    // 0: zero, 1-2: weight splits, 3-5: input GEMMs (ncu -s 5 lands on gemmV)
    zero_kv<<<(B_ * H_ * DK_ * DK_ + 255) / 256, 256>>>();
    split_w2<<<2048, 256>>>(Wq, whp + 0 * WS, wlp + 0 * WS,
                            Wk, whp + 1 * WS, wlp + 1 * WS);
    split_w2<<<2048, 256>>>(Wv, whp + 2 * WS, wlp + 2 * WS,
                            Wo, whp + 3 * WS, wlp + 3 * WS);

    gemm_tc<0><<<gg, 256, SMEMSZ>>>(q, php, plp, whp + 0 * WS, wlp + 0 * WS, Qb, 1);
    gemm_tc<0><<<gg, 256, SMEMSZ>>>(k, php, plp, whp + 1 * WS, wlp + 1 * WS, Kb, 1);
    gemm_tc<0><<<gg, 256, SMEMSZ>>>(v, php, plp, whp + 2 * WS, wlp + 2 * WS, Vb, 0);

    kv_reduce<<<dim3(B_ * H_, S_ / SCHUNK), 256>>>(Kb, Vb);
    apply_kv<<<dim3(B_ * H_, S_ / SC3), 256>>>(Qb, php, plp);

    gemm_tc<1><<<gg, 256, SMEMSZ>>>(nullptr, php, plp, whp + 3 * WS, wlp + 3 * WS,
                                    out, 0);
}